// round 3
// baseline (speedup 1.0000x reference)
#include <cuda_runtime.h>

#define NB 8
#define NT 256   // TE == TD
#define ND 256
#define NU 256

// Scratch (no allocations allowed in kernel_launch)
__device__ float g_ae[NB*NT*NU];      // (B*TE, U)
__device__ float g_ad[NB*NT*NU];      // (B*TD, U)
__device__ float g_alphas[NB*NT*NT];  // (B, TD, TE)
__device__ float g_maxmu[NB*NT];      // (B, TD)
__device__ float g_hhat[NB*ND];       // (B, D)

__device__ __forceinline__ float tanh_fast(float x){
    float y; asm("tanh.approx.f32 %0, %1;" : "=f"(y) : "f"(x)); return y;
}

// ---------------------------------------------------------------------------
// K1: ae = en @ w_en, ad = de @ w_de.
// grid 1024: blocks [0,512) -> ae, [512,1024) -> ad. Each block: 4 rows.
// 256 threads: ty = tid/64 (row), tx = tid%64 (u-group of 4, float4 on w).
// ---------------------------------------------------------------------------
__global__ void __launch_bounds__(256) k1_proj(
    const float* __restrict__ en, const float* __restrict__ de,
    const float* __restrict__ w_en, const float* __restrict__ w_de)
{
    __shared__ float s_in[4*256];
    int bb = blockIdx.x;
    bool isA = bb < 512;
    int rb = (isA ? bb : bb - 512) * 4;            // row base in [0,2048)
    const float* in = isA ? en : de;
    const float* w  = isA ? w_en : w_de;
    float* out      = isA ? g_ae : g_ad;

    // cooperative load of 4 input rows (1024 floats = 256 float4)
    ((float4*)s_in)[threadIdx.x] = ((const float4*)(in + rb*ND))[threadIdx.x];
    __syncthreads();

    int ty = threadIdx.x >> 6;        // 0..3
    int tx = threadIdx.x & 63;        // 0..63 (u-group)
    const float* srow = s_in + ty*ND;
    const float4* w4 = (const float4*)w;

    float4 acc = make_float4(0.f,0.f,0.f,0.f);
    #pragma unroll 8
    for (int d = 0; d < ND; d++){
        float  x  = srow[d];
        float4 wv = w4[d*64 + tx];
        acc.x = fmaf(x, wv.x, acc.x);
        acc.y = fmaf(x, wv.y, acc.y);
        acc.z = fmaf(x, wv.z, acc.z);
        acc.w = fmaf(x, wv.w, acc.w);
    }
    ((float4*)(out + (rb + ty)*NU))[tx] = acc;
}

// ---------------------------------------------------------------------------
// K2: mu[b,s,t] = sum_u tanh(ad[b,s,u] + ae[b,t,u]) * nu[u]
//     then rowwise softmax over t -> g_alphas; rowmax -> g_maxmu.
// grid 512: block = (b, 4 consecutive s rows). 256 threads = 8 warps.
// Warp w handles t = ti*8 + w. Lane l handles u = l + 32k, k=0..7.
// ad & nu held in registers so each ae load feeds 4 tanh (s-reuse).
// ---------------------------------------------------------------------------
__global__ void __launch_bounds__(256) k2_mu(const float* __restrict__ nu)
{
    __shared__ float s_mu[4][256];
    int blk  = blockIdx.x;
    int b    = blk >> 6;              // 64 blocks per batch
    int s0   = (blk & 63) * 4;
    int lane = threadIdx.x & 31;
    int w    = threadIdx.x >> 5;

    float nur[8], adr0[8], adr1[8], adr2[8], adr3[8];
    #pragma unroll
    for (int k = 0; k < 8; k++) nur[k] = nu[lane + 32*k];
    const float* adb = g_ad + (b*NT + s0)*NU;
    #pragma unroll
    for (int k = 0; k < 8; k++){
        int u = lane + 32*k;
        adr0[k] = adb[0*NU + u];
        adr1[k] = adb[1*NU + u];
        adr2[k] = adb[2*NU + u];
        adr3[k] = adb[3*NU + u];
    }
    const float* aeb = g_ae + b*NT*NU;

    for (int ti = 0; ti < 32; ti++){
        int t = ti*8 + w;
        const float* aet = aeb + t*NU;
        float a0=0.f, a1=0.f, a2=0.f, a3=0.f;
        #pragma unroll
        for (int k = 0; k < 8; k++){
            float a = aet[lane + 32*k];
            a0 = fmaf(tanh_fast(adr0[k] + a), nur[k], a0);
            a1 = fmaf(tanh_fast(adr1[k] + a), nur[k], a1);
            a2 = fmaf(tanh_fast(adr2[k] + a), nur[k], a2);
            a3 = fmaf(tanh_fast(adr3[k] + a), nur[k], a3);
        }
        #pragma unroll
        for (int off = 16; off; off >>= 1){
            a0 += __shfl_xor_sync(0xffffffffu, a0, off);
            a1 += __shfl_xor_sync(0xffffffffu, a1, off);
            a2 += __shfl_xor_sync(0xffffffffu, a2, off);
            a3 += __shfl_xor_sync(0xffffffffu, a3, off);
        }
        if (lane == 0){
            s_mu[0][t] = a0; s_mu[1][t] = a1;
            s_mu[2][t] = a2; s_mu[3][t] = a3;
        }
    }
    __syncthreads();

    // softmax over t for each of the 4 s rows; warps 0..3 each own one row
    if (w < 4){
        int s = w;
        float v[8];
        float m = -1e30f;
        #pragma unroll
        for (int j = 0; j < 8; j++){ v[j] = s_mu[s][lane + 32*j]; m = fmaxf(m, v[j]); }
        #pragma unroll
        for (int off = 16; off; off >>= 1) m = fmaxf(m, __shfl_xor_sync(0xffffffffu, m, off));
        float sum = 0.f;
        #pragma unroll
        for (int j = 0; j < 8; j++){ v[j] = __expf(v[j] - m); sum += v[j]; }
        #pragma unroll
        for (int off = 16; off; off >>= 1) sum += __shfl_xor_sync(0xffffffffu, sum, off);
        float inv = 1.0f / sum;
        float* arow = g_alphas + (b*NT + s0 + s)*NT;
        #pragma unroll
        for (int j = 0; j < 8; j++) arow[lane + 32*j] = v[j] * inv;
        if (lane == 0) g_maxmu[b*NT + s0 + s] = m;
    }
}

// ---------------------------------------------------------------------------
// K3: max_alphas = softmax over s of max_mu[b,:]; h_hat[b,d] = sum_s de*ma.
// grid NB, 256 threads (tid = s for softmax, tid = d for h_hat).
// ---------------------------------------------------------------------------
__global__ void __launch_bounds__(256) k3_hhat(const float* __restrict__ de)
{
    __shared__ float s_ma[256];
    __shared__ float s_red[8];
    int b = blockIdx.x;
    int tid = threadIdx.x, lane = tid & 31, w = tid >> 5;

    float v = g_maxmu[b*NT + tid];
    float m = v;
    #pragma unroll
    for (int off = 16; off; off >>= 1) m = fmaxf(m, __shfl_xor_sync(0xffffffffu, m, off));
    if (lane == 0) s_red[w] = m;
    __syncthreads();
    m = s_red[0];
    #pragma unroll
    for (int i = 1; i < 8; i++) m = fmaxf(m, s_red[i]);
    __syncthreads();

    float e = __expf(v - m);
    float psum = e;
    #pragma unroll
    for (int off = 16; off; off >>= 1) psum += __shfl_xor_sync(0xffffffffu, psum, off);
    if (lane == 0) s_red[w] = psum;
    __syncthreads();
    float tot = 0.f;
    #pragma unroll
    for (int i = 0; i < 8; i++) tot += s_red[i];
    s_ma[tid] = e / tot;
    __syncthreads();

    // h_hat: thread d accumulates over s
    int d = tid;
    const float* deb = de + b*NT*ND;
    float acc = 0.f;
    #pragma unroll 4
    for (int s = 0; s < NT; s++) acc = fmaf(deb[s*ND + d], s_ma[s], acc);
    g_hhat[b*ND + d] = acc;
}

// ---------------------------------------------------------------------------
// K4: sum_en[b,s,:] = alphas[b,s,:] @ en[b] ; assemble output concat.
// grid 512: block = (b, 4 s rows). Thread d. alphas staged transposed in
// shared as float4 so each en load feeds 4 FMAs and one LDS.128 broadcast.
// ---------------------------------------------------------------------------
__global__ void __launch_bounds__(256) k4_out(
    const float* __restrict__ en, const float* __restrict__ de,
    float* __restrict__ out)
{
    __shared__ float4 s_a[256];   // [t] -> (a_s0, a_s1, a_s2, a_s3)
    int blk = blockIdx.x;
    int b   = blk >> 6;
    int s0  = (blk & 63) * 4;
    int tid = threadIdx.x;

    {
        const float* ab = g_alphas + (b*NT + s0)*NT;
        float4 av;
        av.x = ab[0*NT + tid];
        av.y = ab[1*NT + tid];
        av.z = ab[2*NT + tid];
        av.w = ab[3*NT + tid];
        s_a[tid] = av;
    }
    __syncthreads();

    const float* enb = en + b*NT*ND;
    int d = tid;
    float c0=0.f, c1=0.f, c2=0.f, c3=0.f;
    #pragma unroll 8
    for (int t = 0; t < NT; t++){
        float  e = enb[t*ND + d];
        float4 a = s_a[t];
        c0 = fmaf(a.x, e, c0);
        c1 = fmaf(a.y, e, c1);
        c2 = fmaf(a.z, e, c2);
        c3 = fmaf(a.w, e, c3);
    }

    float hh = g_hhat[b*ND + d];
    float accs[4] = {c0, c1, c2, c3};
    #pragma unroll
    for (int s = 0; s < 4; s++){
        int row = b*NT + s0 + s;
        float dv = de[row*ND + d];
        float* o = out + (size_t)row * (4*ND);
        o[0*ND + d] = dv;
        o[1*ND + d] = accs[s];
        o[2*ND + d] = dv * accs[s];
        o[3*ND + d] = dv * hh;
    }
}

extern "C" void kernel_launch(void* const* d_in, const int* in_sizes, int n_in,
                              void* d_out, int out_size)
{
    const float* en   = (const float*)d_in[0];
    const float* de   = (const float*)d_in[1];
    const float* w_en = (const float*)d_in[2];
    const float* w_de = (const float*)d_in[3];
    const float* nu   = (const float*)d_in[4];
    float* out = (float*)d_out;

    k1_proj<<<1024, 256>>>(en, de, w_en, w_de);
    k2_mu  <<<512,  256>>>(nu);
    k3_hhat<<<NB,   256>>>(de);
    k4_out <<<512,  256>>>(en, de, out);
}